// round 16
// baseline (speedup 1.0000x reference)
#include <cuda_runtime.h>
#include <cuda_fp16.h>
#include <cstdint>

#define BSZN 8
#define HD   512
#define PD   128
#define LEN  8192
#define M2   256

// ---------------- scratch (no allocations allowed) ----------------
__device__ __align__(128) float  g_bu[(size_t)BSZN * M2 * LEN];     // 64 MB Bu fp32
__device__ __align__(128) __half g_uhi[(size_t)BSZN * HD * LEN];    // u as fp16
__device__ __align__(128) __half g_xhi[(size_t)BSZN * M2 * LEN];    // xs as fp16
__device__ __align__(128) __half g_w1h[M2 * HD];                    // weights fp16
__device__ __align__(128) __half g_w2h[HD * M2];
__device__ float g_lam_re[PD];
__device__ float g_lam_im[PD];

// ---------------- helpers ----------------
__device__ __forceinline__ uint32_t smem_u32(const void* p) {
    uint32_t a;
    asm("{ .reg .u64 t; cvta.to.shared.u64 t, %1; cvt.u32.u64 %0, t; }" : "=r"(a) : "l"(p));
    return a;
}
__device__ __forceinline__ float gelu_exact(float x) {
    return 0.5f * x * (1.0f + erff(x * 0.70710678118654752f));
}
__device__ __forceinline__ void ldsm_x4(uint32_t (&r)[4], uint32_t addr) {
    asm volatile("ldmatrix.sync.aligned.m8n8.x4.shared.b16 {%0,%1,%2,%3}, [%4];"
                 : "=r"(r[0]), "=r"(r[1]), "=r"(r[2]), "=r"(r[3]) : "r"(addr));
}
__device__ __forceinline__ void ldsm_x4_t(uint32_t (&r)[4], uint32_t addr) {
    asm volatile("ldmatrix.sync.aligned.m8n8.x4.trans.shared.b16 {%0,%1,%2,%3}, [%4];"
                 : "=r"(r[0]), "=r"(r[1]), "=r"(r[2]), "=r"(r[3]) : "r"(addr));
}
__device__ __forceinline__ void mma_fp16(float (&c)[4], const uint32_t (&a)[4],
                                         const uint32_t* b) {
    asm volatile("mma.sync.aligned.m16n8k16.row.col.f32.f16.f16.f32 "
                 "{%0,%1,%2,%3},{%4,%5,%6,%7},{%8,%9},{%0,%1,%2,%3};"
                 : "+f"(c[0]), "+f"(c[1]), "+f"(c[2]), "+f"(c[3])
                 : "r"(a[0]), "r"(a[1]), "r"(a[2]), "r"(a[3]), "r"(b[0]), "r"(b[1]));
}
__device__ __forceinline__ void cp16(uint32_t saddr, const void* g) {
    asm volatile("cp.async.cg.shared.global [%0], [%1], 16;" :: "r"(saddr), "l"(g));
}
#define CP_COMMIT() asm volatile("cp.async.commit_group;" ::: "memory")
#define CP_WAIT1()  asm volatile("cp.async.wait_group 1;" ::: "memory")

// ---------------------------------------------------------------------------
// Precompute: Lambda_bar; weights as fp16.
// ---------------------------------------------------------------------------
__global__ void precompute_kernel(const float* __restrict__ lre,
                                  const float* __restrict__ lim,
                                  const float* __restrict__ Bp,
                                  const float* __restrict__ Cp,
                                  const float* __restrict__ ls) {
    int idx = blockIdx.x * blockDim.x + threadIdx.x;   // [0, 65536)
    {   // W1: p = idx>>9, hcol = idx&511
        int p = idx >> 9, hcol = idx & 511;
        float ar = lre[p], ai = lim[p];
        float st = expf(ls[p]);
        float er = expf(ar * st);
        float sb, cb; sincosf(ai * st, &sb, &cb);
        float lbr = er * cb, lbi = er * sb;
        float nr = lbr - 1.0f, ni = lbi;
        float den = ar * ar + ai * ai;
        float cr = (nr * ar + ni * ai) / den;
        float ci = (ni * ar - nr * ai) / den;
        float btr = Bp[(p * HD + hcol) * 2 + 0];
        float bti = Bp[(p * HD + hcol) * 2 + 1];
        g_w1h[p * HD + hcol]        = __float2half_rn(cr * btr - ci * bti);
        g_w1h[(p + PD) * HD + hcol] = __float2half_rn(cr * bti + ci * btr);
    }
    if (idx < PD) {
        float ar = lre[idx], ai = lim[idx];
        float st = expf(ls[idx]);
        float er = expf(ar * st);
        float sb, cb; sincosf(ai * st, &sb, &cb);
        g_lam_re[idx] = er * cb;
        g_lam_im[idx] = er * sb;
    }
    {   // W2: hrow = idx>>7, p = idx&127
        int hrow = idx >> 7, p = idx & 127;
        g_w2h[hrow * M2 + p]      = __float2half_rn( 2.0f * Cp[(hrow * PD + p) * 2 + 0]);
        g_w2h[hrow * M2 + p + PD] = __float2half_rn(-2.0f * Cp[(hrow * PD + p) * 2 + 1]);
    }
}

// ---------------------------------------------------------------------------
// Convert u (fp32) -> fp16. 33.5M elems, float4 per thread.
// ---------------------------------------------------------------------------
__global__ __launch_bounds__(256)
void conv_u_kernel(const float* __restrict__ u) {
    size_t i = ((size_t)blockIdx.x * 256 + threadIdx.x) * 4;
    float4 v = *(const float4*)&u[i];
    ushort4 hw = make_ushort4(__half_as_ushort(__float2half_rn(v.x)),
                              __half_as_ushort(__float2half_rn(v.y)),
                              __half_as_ushort(__float2half_rn(v.z)),
                              __half_as_ushort(__float2half_rn(v.w)));
    *(ushort4*)&g_uhi[i] = hw;
}

// ---------------------------------------------------------------------------
// mma.sync fp16 GEMM, single product. K-chunk 64, 3 stages, wait 1,
// compute-then-issue (R8-proven shape). CTA tile 128x128, 8 warps (4m x 2n).
// Stage: A(16K) B(16K) = 32KB; 3 stages = 96KB; 2 CTAs/SM.
// ---------------------------------------------------------------------------
#define ABUF   16384
#define BUFSZ  32768
#define STAGES 3
#define GSMEM  (STAGES * BUFSZ)

template<bool SECOND>
__global__ __launch_bounds__(256, 2)
void mgemm_kernel(const __half* __restrict__ Bsrc,
                  const float* __restrict__ uin,
                  float* __restrict__ outp,
                  const float* __restrict__ Dvec) {
    constexpr int KDIM = SECOND ? M2 : HD;
    constexpr int NCH  = KDIM / 64;      // GEMM1: 8, GEMM2: 4

    extern __shared__ __align__(128) char smem[];
    const uint32_t sbase = smem_u32(smem);

    const int tid  = threadIdx.x;
    const int wid  = tid >> 5;
    const int lane = tid & 31;
    const int warp_m = wid & 3;
    const int warp_n = wid >> 2;
    const int m0 = blockIdx.x * 128;
    const int n0 = blockIdx.y * 128;
    const int z  = blockIdx.z;

    const __half* Wh = SECOND ? g_w2h : g_w1h;
    const size_t Bofs = (size_t)z * KDIM * LEN;
    const size_t Cofs = (size_t)z * (SECOND ? HD : M2) * LEN;

    // staging maps: A rows of 128B (64 fp16), B rows of 256B (128 fp16)
    const int sAr = tid >> 1, sAh = tid & 1;       // A: row 0..127, 64B half
    const int sBk = tid >> 2, sBn = tid & 3;       // B: k-row 0..63, quarter row
    uint32_t aoff[4], boff[4];
    #pragma unroll
    for (int j = 0; j < 4; j++) {
        aoff[j] = (uint32_t)(sAr * 128 + (((sAh * 4 + j) ^ (sAr & 7)) << 4));
        boff[j] = (uint32_t)(ABUF + sBk * 256 + (((sBn * 4 + j) ^ (sBk & 7)) << 4));
    }

    auto issue_commit = [&](int ci) {
        if (ci < NCH) {
            const int k0 = ci * 64;
            const uint32_t bb = sbase + (uint32_t)(ci % STAGES) * BUFSZ;
            const __half* gA = Wh + (size_t)(m0 + sAr) * KDIM + k0 + sAh * 32;
            #pragma unroll
            for (int j = 0; j < 4; j++) cp16(bb + aoff[j], gA + j * 8);
            const __half* gB = Bsrc + Bofs + (size_t)(k0 + sBk) * LEN + n0 + sBn * 32;
            #pragma unroll
            for (int j = 0; j < 4; j++) cp16(bb + boff[j], gB + j * 8);
        }
        CP_COMMIT();
    };

    float acc[2][8][4];
    #pragma unroll
    for (int a = 0; a < 2; a++)
        #pragma unroll
        for (int b = 0; b < 8; b++)
            #pragma unroll
            for (int c = 0; c < 4; c++) acc[a][b][c] = 0.0f;

    const int lrow8 = (lane & 7) + ((lane >> 3) & 1) * 8;   // 0..15
    const int lhalf = (lane >> 4) & 1;                      // 0/1

    auto compute = [&](uint32_t bb) {
        #pragma unroll
        for (int ks = 0; ks < 4; ks++) {
            uint32_t Am[2][4];
            #pragma unroll
            for (int mt = 0; mt < 2; mt++) {
                int row = warp_m * 32 + mt * 16 + lrow8;
                int c = ks * 2 + lhalf;
                uint32_t addr = sbase + bb + row * 128 + ((c ^ (row & 7)) << 4);
                ldsm_x4(Am[mt], addr);
            }
            #pragma unroll
            for (int nt = 0; nt < 4; nt++) {
                int krow = ks * 16 + lrow8;
                int noff = warp_n * 64 + nt * 16 + lhalf * 8;
                int c = noff >> 3;
                uint32_t addr = sbase + bb + ABUF + krow * 256 +
                                ((c ^ (krow & 7)) << 4);
                uint32_t Bh[4];
                ldsm_x4_t(Bh, addr);
                #pragma unroll
                for (int mt = 0; mt < 2; mt++) {
                    mma_fp16(acc[mt][2*nt + 0], Am[mt], &Bh[0]);
                    mma_fp16(acc[mt][2*nt + 1], Am[mt], &Bh[2]);
                }
            }
        }
    };

    issue_commit(0);
    issue_commit(1);
    for (int i = 0; i < NCH; i++) {
        CP_WAIT1();               // group for chunk i complete
        __syncthreads();
        compute((uint32_t)(i % STAGES) * BUFSZ);
        issue_commit(i + 2);      // refills slot (i-1)%3, consumed at iter i-1
    }

    // ---------------- epilogue ----------------
    const int g = lane >> 2, t4 = lane & 3;
    #pragma unroll
    for (int mt = 0; mt < 2; mt++) {
        #pragma unroll
        for (int nt8 = 0; nt8 < 8; nt8++) {
            int col = n0 + warp_n * 64 + nt8 * 8 + t4 * 2;
            #pragma unroll
            for (int h = 0; h < 2; h++) {
                int row = m0 + warp_m * 32 + mt * 16 + g + h * 8;
                size_t off = Cofs + (size_t)row * LEN + col;
                float v0 = acc[mt][nt8][2*h + 0];
                float v1 = acc[mt][nt8][2*h + 1];
                if (SECOND) {
                    float d = __ldg(&Dvec[row]);
                    float2 uu = *(const float2*)&uin[(size_t)z * HD * LEN +
                                                     (size_t)row * LEN + col];
                    v0 = gelu_exact(v0 + d * uu.x);
                    v1 = gelu_exact(v1 + d * uu.y);
                    float2 st; st.x = v0; st.y = v1;
                    *(float2*)&outp[off] = st;
                } else {
                    float2 st; st.x = v0; st.y = v1;
                    *(float2*)&g_bu[off] = st;
                }
            }
        }
    }
}

// ---------------------------------------------------------------------------
// Scan: x_l = a*x_{l-1} + b_l, complex diagonal, one block per (b,p) channel.
// Warp-shuffle carry scan: 5 syncs/chunk instead of 19.
// Reads Bu fp32 from g_bu; writes xs fp16 to g_xhi.
// ---------------------------------------------------------------------------
__global__ __launch_bounds__(256)
void scan_kernel() {
    int ch = blockIdx.x;
    int b = ch >> 7, p = ch & 127;
    const float ar = g_lam_re[p];
    const float ai = g_lam_im[p];

    const size_t rre = ((size_t)b * M2 + p) * LEN;
    const size_t rim = ((size_t)b * M2 + p + PD) * LEN;
    const float* bre = g_bu + rre;
    const float* bim = g_bu + rim;

    __shared__ float sre[2112], sim[2112];
    __shared__ float wtr[8], wti[8];
    __shared__ float wpr[8], wpi[8];
    __shared__ float s_cr, s_ci;

    const int t = threadIdx.x, lane = t & 31, w = t >> 5;

    // m = a^8; M[s] = m^(2^s), s=0..4; a256 = m^32
    float Mr[5], Mi[5];
    {
        float xr = ar, xi = ai;
        #pragma unroll
        for (int s = 0; s < 3; s++) { float nr = xr*xr - xi*xi, ni = 2.f*xr*xi; xr = nr; xi = ni; }
        Mr[0] = xr; Mi[0] = xi;
        #pragma unroll
        for (int s = 1; s < 5; s++) {
            Mr[s] = Mr[s-1]*Mr[s-1] - Mi[s-1]*Mi[s-1];
            Mi[s] = 2.f*Mr[s-1]*Mi[s-1];
        }
    }
    const float a256r = Mr[4]*Mr[4] - Mi[4]*Mi[4];
    const float a256i = 2.f*Mr[4]*Mi[4];
    // per-lane m^lane
    float plr = 1.f, pli = 0.f;
    #pragma unroll
    for (int s = 0; s < 5; s++)
        if ((lane >> s) & 1) {
            float nr = plr*Mr[s] - pli*Mi[s], ni = plr*Mi[s] + pli*Mr[s];
            plr = nr; pli = ni;
        }

    if (t == 0) { s_cr = 0.f; s_ci = 0.f; }
    __syncthreads();

    const int base = t * 8;
    for (int c0 = 0; c0 < LEN; c0 += 2048) {
        for (int j = t * 2; j < 2048; j += 512) {
            float2 vr = *(const float2*)&bre[c0 + j];
            float2 vi = *(const float2*)&bim[c0 + j];
            int jj = j + (j >> 5);
            sre[jj] = vr.x; sre[jj + 1] = vr.y;
            sim[jj] = vi.x; sim[jj + 1] = vi.y;
        }
        __syncthreads();

        // segment end (zero carry-in)
        float er = 0.f, ei = 0.f;
        #pragma unroll
        for (int i = 0; i < 8; i++) {
            int idx = base + i; idx += idx >> 5;
            float br = sre[idx], bi = sim[idx];
            float nr = ar*er - ai*ei + br;
            float ni = ar*ei + ai*er + bi;
            er = nr; ei = ni;
        }
        // warp inclusive scan of segment values
        #pragma unroll
        for (int s = 0; s < 5; s++) {
            int off = 1 << s;
            float pr = __shfl_up_sync(0xffffffffu, er, off);
            float pi = __shfl_up_sync(0xffffffffu, ei, off);
            if (lane >= off) {
                er += Mr[s]*pr - Mi[s]*pi;
                ei += Mr[s]*pi + Mi[s]*pr;
            }
        }
        float exr = __shfl_up_sync(0xffffffffu, er, 1);
        float exi = __shfl_up_sync(0xffffffffu, ei, 1);
        if (lane == 31) { wtr[w] = er; wti[w] = ei; }
        __syncthreads();

        if (t == 0) {
            float cr = s_cr, ci = s_ci;
            #pragma unroll
            for (int w2 = 0; w2 < 8; w2++) {
                wpr[w2] = cr; wpi[w2] = ci;
                float nr = a256r*cr - a256i*ci + wtr[w2];
                float ni = a256r*ci + a256i*cr + wti[w2];
                cr = nr; ci = ni;
            }
            s_cr = cr; s_ci = ci;
        }
        __syncthreads();

        // carry into my segment = m^lane * P_w + exclusive-within-warp
        float Pr = wpr[w], Pi = wpi[w];
        float xr = plr*Pr - pli*Pi;
        float xi = plr*Pi + pli*Pr;
        if (lane > 0) { xr += exr; xi += exi; }
        // replay with true carry
        #pragma unroll
        for (int i = 0; i < 8; i++) {
            int idx = base + i; idx += idx >> 5;
            float br = sre[idx], bi = sim[idx];
            float nr = ar*xr - ai*xi + br;
            float ni = ar*xi + ai*xr + bi;
            xr = nr; xi = ni;
            sre[idx] = xr; sim[idx] = xi;
        }
        __syncthreads();

        for (int j = t * 2; j < 2048; j += 512) {
            int jj = j + (j >> 5);
            *(__half2*)&g_xhi[rre + c0 + j] = __floats2half2_rn(sre[jj], sre[jj + 1]);
            *(__half2*)&g_xhi[rim + c0 + j] = __floats2half2_rn(sim[jj], sim[jj + 1]);
        }
        __syncthreads();
    }
}

// ---------------------------------------------------------------------------
extern "C" void kernel_launch(void* const* d_in, const int* in_sizes, int n_in,
                              void* d_out, int out_size) {
    const float* u   = (const float*)d_in[0];   // (8,1,512,1,8192)
    const float* lre = (const float*)d_in[1];
    const float* lim = (const float*)d_in[2];
    const float* B   = (const float*)d_in[3];
    const float* C   = (const float*)d_in[4];
    const float* D   = (const float*)d_in[5];
    const float* ls  = (const float*)d_in[6];
    float* out = (float*)d_out;

    cudaFuncSetAttribute(mgemm_kernel<false>,
                         cudaFuncAttributeMaxDynamicSharedMemorySize, GSMEM);
    cudaFuncSetAttribute(mgemm_kernel<true>,
                         cudaFuncAttributeMaxDynamicSharedMemorySize, GSMEM);

    __half *uhi, *xhi;
    cudaGetSymbolAddress((void**)&uhi, g_uhi);
    cudaGetSymbolAddress((void**)&xhi, g_xhi);

    precompute_kernel<<<256, 256>>>(lre, lim, B, C, ls);
    conv_u_kernel<<<32768, 256>>>(u);   // 32768*256*4 = 33.5M = BSZN*HD*LEN
    mgemm_kernel<false><<<dim3(2, 64, BSZN), 256, GSMEM>>>(uhi, u, nullptr, nullptr);
    scan_kernel<<<1024, 256>>>();
    mgemm_kernel<true><<<dim3(4, 64, BSZN), 256, GSMEM>>>(xhi, u, out, D);
}